// round 13
// baseline (speedup 1.0000x reference)
#include <cuda_runtime.h>
#include <cuda_bf16.h>

#define N_NODES    100000
#define OUTPUT_DIM 128
#define MAX_NNZ    2000000
#define KEEP_INV   (1.0f / 0.9f)

// Static device scratch (no allocations allowed)
__device__ int    g_row_start[N_NODES + 1]; // CSR row pointers
__device__ float2 g_packed[MAX_NNZ];        // (v*KEEP_INV or 0, col-as-float-bits)

__device__ __forceinline__ void fill_rowptr(int rprev, int r, int i) {
    for (int x = rprev + 1; x <= r; ++x) g_row_start[x] = i;
}

// ---------------------------------------------------------------------------
// Kernel 1 (fused prologue, x4 vectorized — unchanged, known good): per nnz i
// build CSR rowptr from sorted rows and pack (keep ? v/keep_prob : 0, colbits).
// Mask dtype detected per block from the same 256-element window (identical
// answer in every block -> deterministic).
// ---------------------------------------------------------------------------
__global__ void __launch_bounds__(256)
pack_and_rowptr_kernel(const float* __restrict__ values,
                       const int*   __restrict__ rows,
                       const int*   __restrict__ cols,
                       const unsigned char* __restrict__ m,
                       int nnz)
{
    // ---- per-block mask dtype detect (identical in every block) ----
    __shared__ int s_cnt[2][8];
    __shared__ int s_mode;
    {
        const int tid = threadIdx.x;
        const int n   = nnz < 256 ? nnz : 256;
        const int* mi = (const int*)m;

        int u8 = 0, i32 = 0;
        if (tid < n) {
            if (m[tid]  == 1) u8++;
            if (mi[tid] == 1) i32++;
        }
        #pragma unroll
        for (int off = 16; off > 0; off >>= 1) {
            u8  += __shfl_down_sync(0xffffffffu, u8,  off);
            i32 += __shfl_down_sync(0xffffffffu, i32, off);
        }
        const int wid = tid >> 5, lane = tid & 31;
        if (lane == 0) { s_cnt[0][wid] = u8; s_cnt[1][wid] = i32; }
        __syncthreads();
        if (tid == 0) {
            int tu8 = 0, ti32 = 0;
            #pragma unroll
            for (int w = 0; w < 8; ++w) { tu8 += s_cnt[0][w]; ti32 += s_cnt[1][w]; }
            int mode;
            if (tu8 * 4 > n * 3)       mode = 0;     // byte mask
            else if (ti32 * 4 > n * 3) mode = 1;     // int32 mask
            else                       mode = 2;     // float32 mask
            s_mode = mode;
        }
        __syncthreads();
    }
    const int mode = s_mode;

    const int base = (blockIdx.x * blockDim.x + threadIdx.x) * 4;
    if (base >= nnz) return;

    if (base + 4 <= nnz) {
        const int4   r4 = *(const int4*)(rows + base);
        const float4 v4 = *(const float4*)(values + base);
        const int4   c4 = *(const int4*)(cols + base);

        const int rprev = (base == 0) ? -1 : rows[base - 1];
        fill_rowptr(rprev, r4.x, base + 0);
        fill_rowptr(r4.x,  r4.y, base + 1);
        fill_rowptr(r4.y,  r4.z, base + 2);
        fill_rowptr(r4.z,  r4.w, base + 3);
        if (base + 4 == nnz) fill_rowptr(r4.w, N_NODES, nnz);

        bool k0, k1, k2, k3;
        if (mode == 0) {
            const uchar4 mm = *(const uchar4*)(m + base);
            k0 = mm.x != 0; k1 = mm.y != 0; k2 = mm.z != 0; k3 = mm.w != 0;
        } else if (mode == 1) {
            const int4 mm = *(const int4*)((const int*)m + base);
            k0 = mm.x != 0; k1 = mm.y != 0; k2 = mm.z != 0; k3 = mm.w != 0;
        } else {
            const float4 mm = *(const float4*)((const float*)m + base);
            k0 = mm.x != 0.0f; k1 = mm.y != 0.0f; k2 = mm.z != 0.0f; k3 = mm.w != 0.0f;
        }

        float4 p01, p23;
        p01.x = k0 ? v4.x * KEEP_INV : 0.0f;  p01.y = __int_as_float(c4.x);
        p01.z = k1 ? v4.y * KEEP_INV : 0.0f;  p01.w = __int_as_float(c4.y);
        p23.x = k2 ? v4.z * KEEP_INV : 0.0f;  p23.y = __int_as_float(c4.z);
        p23.z = k3 ? v4.w * KEEP_INV : 0.0f;  p23.w = __int_as_float(c4.w);
        float4* dst = (float4*)(g_packed + base);
        dst[0] = p01;
        dst[1] = p23;
    } else {
        for (int i = base; i < nnz; ++i) {
            const int r = rows[i];
            const int rprev = (i == 0) ? -1 : rows[i - 1];
            fill_rowptr(rprev, r, i);
            if (i == nnz - 1) fill_rowptr(r, N_NODES, nnz);

            bool keep;
            if (mode == 0)      keep = m[i] != 0;
            else if (mode == 1) keep = ((const int*)m)[i] != 0;
            else                keep = ((const float*)m)[i] != 0.0f;
            const float v = keep ? values[i] * KEEP_INV : 0.0f;
            g_packed[i] = make_float2(v, __int_as_float(cols[i]));
        }
    }
}

// ---------------------------------------------------------------------------
// Kernel 2: TWO rows per warp, lane l owns output columns [4l, 4l+4) of both.
//
// The two rows give each warp two INDEPENDENT memory dependency chains at a
// cost of only ~1 extra accumulator + cursor (~36 regs total), so occupancy
// stays high (the R12 mistake: buying MLP with a reg-ceiling that halved
// resident rows). Padded branchless loop: iterate max(lenA, lenB); indices
// clamp to nnz-1 (always an initialized g_packed entry -> valid col ->
// safe gather) and out-of-range contributions are selected to v=0, so the
// body is straight-line and both gathers issue back-to-back every iteration.
// Exclusive row ownership -> plain float4 stores, bias fused, no atomics.
// ---------------------------------------------------------------------------
__global__ void __launch_bounds__(256)
spmm_two_rows_kernel(const float4* __restrict__ W4,     // [INPUT_DIM][32] float4
                     const float4* __restrict__ bias4,  // [32] float4
                     float4* __restrict__ out4,         // [N_NODES][32] float4
                     int nnz)
{
    const int warp = (blockIdx.x * blockDim.x + threadIdx.x) >> 5;
    const int lane = threadIdx.x & 31;
    const int rA = warp * 2;
    if (rA >= N_NODES) return;
    const int rB = rA + 1;
    const int nnzm1 = nnz - 1;

    const int sA = g_row_start[rA];
    const int eA = g_row_start[rA + 1];
    int sB = 0, eB = 0;
    if (rB < N_NODES) { sB = eA; eB = g_row_start[rB + 1]; }

    const float4 bias = bias4[lane];
    float4 accA = bias;
    float4 accB = make_float4(0.f, 0.f, 0.f, 0.f);

    int kA = sA, kB = sB;
    const int lenA = eA - sA;
    const int lenB = eB - sB;
    int iters = lenA > lenB ? lenA : lenB;

    for (; iters > 0; --iters) {
        const int iA = kA < nnzm1 ? kA : nnzm1;      // always-initialized entry
        const int iB = kB < nnzm1 ? kB : nnzm1;
        const float2 pA = g_packed[iA];              // warp-uniform broadcasts
        const float2 pB = g_packed[iB];
        const float vA = (kA < eA) ? pA.x : 0.0f;    // pad -> contributes 0
        const float vB = (kB < eB) ? pB.x : 0.0f;
        // two independent coalesced 512B gathers, in flight together
        const float4 wA = W4[__float_as_int(pA.y) * 32 + lane];
        const float4 wB = W4[__float_as_int(pB.y) * 32 + lane];

        accA.x += vA * wA.x; accA.y += vA * wA.y; accA.z += vA * wA.z; accA.w += vA * wA.w;
        accB.x += vB * wB.x; accB.y += vB * wB.y; accB.z += vB * wB.z; accB.w += vB * wB.w;
        ++kA; ++kB;
    }

    out4[rA * 32 + lane] = accA;                     // 512B coalesced
    if (rB < N_NODES) {
        accB.x += bias.x; accB.y += bias.y; accB.z += bias.z; accB.w += bias.w;
        out4[rB * 32 + lane] = accB;
    }
}

// ---------------------------------------------------------------------------
// kernel_launch — inputs per setup_inputs() order:
//   0: values  float32 [NNZ]
//   1: rows    int32   [NNZ] (sorted)
//   2: cols    int32   [NNZ]
//   3: keep_mask (bool-ish, dtype auto-detected)
//   4: weights float32 [INPUT_DIM, 128]
//   5: bias    float32 [128]
// ---------------------------------------------------------------------------
extern "C" void kernel_launch(void* const* d_in, const int* in_sizes, int n_in,
                              void* d_out, int out_size)
{
    const float* values = (const float*)d_in[0];
    const int*   rows   = (const int*)  d_in[1];
    const int*   cols   = (const int*)  d_in[2];
    const void*  mask   =               d_in[3];
    const float4* W4    = (const float4*)d_in[4];
    const float4* bias4 = (const float4*)d_in[5];
    float4* out4        = (float4*)d_out;

    const int nnz = in_sizes[0];

    {
        const int threads = 256;
        const int elems_per_block = threads * 4;
        const int blocks = (nnz + elems_per_block - 1) / elems_per_block;
        pack_and_rowptr_kernel<<<blocks, threads>>>(
            values, rows, cols, (const unsigned char*)mask, nnz);
    }

    {
        const int rows_per_block = 16;                 // 8 warps x 2 rows
        const int blocks = (N_NODES + rows_per_block - 1) / rows_per_block;
        spmm_two_rows_kernel<<<blocks, 256>>>(W4, bias4, out4, nnz);
    }
}